// round 1
// baseline (speedup 1.0000x reference)
#include <cuda_runtime.h>

#define N_LAYERS 30
#define T_LEN    262144
#define BATCH    8
#define TILE     7088
#define HALO     576
#define LEXT     (TILE + HALO)          // 7664
#define PADL     32
#define NTH      512
#define NPTS     ((LEXT + NTH - 1) / NTH)   // 15
#define NTILES   ((T_LEN + TILE - 1) / TILE) // 37
#define BUFSZ    (PADL + LEXT)          // 7696
#define WOFF     (2 * BUFSZ)
#define SMEM_FLOATS (WOFF + 448)
#define SMEM_BYTES  (SMEM_FLOATS * 4)

#define LN256 5.545177444479562f

__constant__ int c_dil[N_LAYERS] = {1,2,4,8,6,2,4,8,6,2,4,8,6,2,4,8,6,2,4,8,6,2,4,8,6,2,4,8,6,2};

__device__ float g_tilemax[BATCH * NTILES];
__device__ float g_bmax[BATCH];
__device__ float g_sum[BATCH];

__global__ __launch_bounds__(NTH, 2)
void wavenet_k1(const float* __restrict__ x,
                const float* __restrict__ cw,  const float* __restrict__ cb,
                const float* __restrict__ fw,  const float* __restrict__ fb,
                const float* __restrict__ gw,  const float* __restrict__ gb,
                const float* __restrict__ rw,  const float* __restrict__ rb,
                const float* __restrict__ c1w, const float* __restrict__ c1b,
                const float* __restrict__ c2w, const float* __restrict__ c2b,
                float* __restrict__ out)
{
    extern __shared__ float sh[];
    float* buf0 = sh;                 // [BUFSZ]
    float* buf1 = sh + BUFSZ;         // [BUFSZ]
    float* ws   = sh + WOFF;          // weights

    const int tid  = threadIdx.x;
    const int tile = blockIdx.x;
    const int b    = blockIdx.y;
    const long long base = (long long)b * T_LEN;
    const int g0 = tile * TILE - HALO;     // global pos of smem index i=0
    const bool zh = (tile == 0);           // zero-halo (reference zero-padding) tile

    // ---- load weights into smem ----
    // layout: [0..4]=cw [5]=cb [8..157]=fw [158..187]=fb [188..337]=gw
    //         [338..367]=gb [368..397]=rw [398..427]=rb [428..431]=c1w,c1b,c2w,c2b
    if (tid < 5)  ws[tid] = cw[tid];
    if (tid == 5) ws[5]   = cb[0];
    for (int j = tid; j < 150; j += NTH) { ws[8 + j] = fw[j]; ws[188 + j] = gw[j]; }
    for (int j = tid; j < 30;  j += NTH) {
        ws[158 + j] = fb[j]; ws[338 + j] = gb[j];
        ws[368 + j] = rw[j]; ws[398 + j] = rb[j];
    }
    if (tid == 0) { ws[428] = c1w[0]; ws[429] = c1b[0]; ws[430] = c2w[0]; ws[431] = c2b[0]; }

    // zero left pads (never written again)
    if (tid < PADL) { buf0[tid] = 0.0f; buf1[tid] = 0.0f; }

    // ---- stage x into buf0 ----
    #pragma unroll
    for (int p = 0; p < NPTS; p++) {
        int i = tid + p * NTH;
        if (i < LEXT) {
            int gx = g0 + i;
            buf0[PADL + i] = (gx >= 0 && gx < T_LEN) ? x[base + gx] : 0.0f;
        }
    }
    __syncthreads();

    // ---- causal conv (d=1): buf0 -> buf1 ----
    {
        float w0 = ws[0], w1 = ws[1], w2 = ws[2], w3 = ws[3], w4 = ws[4], bc = ws[5];
        #pragma unroll
        for (int p = 0; p < NPTS; p++) {
            int i = tid + p * NTH;
            if (i < LEXT) {
                const float* s = buf0 + PADL + i;
                float v = bc;
                v = fmaf(w0, s[-4], v);
                v = fmaf(w1, s[-3], v);
                v = fmaf(w2, s[-2], v);
                v = fmaf(w3, s[-1], v);
                v = fmaf(w4, s[ 0], v);
                if (zh && i < HALO) v = 0.0f;   // reproduce global zero-padding
                buf1[PADL + i] = v;
            }
        }
    }
    __syncthreads();

    // ---- 30 gated residual layers ----
    float skip[NPTS];
    #pragma unroll
    for (int p = 0; p < NPTS; p++) skip[p] = 0.0f;

    float* cur = buf1;
    float* nxt = buf0;

    for (int k = 0; k < N_LAYERS; k++) {
        const int d = c_dil[k];
        const float fw0 = ws[8  + 5*k], fw1 = ws[9  + 5*k], fw2 = ws[10 + 5*k],
                    fw3 = ws[11 + 5*k], fw4 = ws[12 + 5*k];
        const float gw0 = ws[188 + 5*k], gw1 = ws[189 + 5*k], gw2 = ws[190 + 5*k],
                    gw3 = ws[191 + 5*k], gw4 = ws[192 + 5*k];
        const float fbk = ws[158 + k], gbk = ws[338 + k];
        const float rwk = ws[368 + k], rbk = ws[398 + k];

        #pragma unroll
        for (int p = 0; p < NPTS; p++) {
            int i = tid + p * NTH;
            if (i < LEXT) {
                const float* s = cur + PADL + i;
                float t0 = s[0], t1 = s[-d], t2 = s[-2*d], t3 = s[-3*d], t4 = s[-4*d];

                float fp = fbk;
                fp = fmaf(fw0, t4, fp); fp = fmaf(fw1, t3, fp); fp = fmaf(fw2, t2, fp);
                fp = fmaf(fw3, t1, fp); fp = fmaf(fw4, t0, fp);
                float gp = gbk;
                gp = fmaf(gw0, t4, gp); gp = fmaf(gw1, t3, gp); gp = fmaf(gw2, t2, gp);
                gp = fmaf(gw3, t1, gp); gp = fmaf(gw4, t0, gp);

                float ef = __expf(-2.0f * fp);
                float f  = __fdividef(2.0f, 1.0f + ef) - 1.0f;   // tanh(fp)
                float eg = __expf(-gp);
                float gg = __fdividef(1.0f, 1.0f + eg);          // sigmoid(gp)

                float z = f * gg;
                skip[p] += z;
                float hn = fmaf(z, rwk, rbk + t0);
                if (zh && i < HALO) hn = 0.0f;
                nxt[PADL + i] = hn;
            }
        }
        __syncthreads();
        float* tmp = cur; cur = nxt; nxt = tmp;
    }

    // ---- epilogue: 1x1 convs + mu-law, write v, track tile max ----
    const float c1wv = ws[428], c1bv = ws[429], c2wv = ws[430], c2bv = ws[431];
    float lmax = -3.402823466e38f;
    #pragma unroll
    for (int p = 0; p < NPTS; p++) {
        int i = tid + p * NTH;
        int g = g0 + i;
        if (i >= HALO && i < LEXT && g < T_LEN) {
            float s = skip[p];
            float r = fmaf(fmaxf(s, 0.0f), c1wv, c1bv);
            r = fmaf(fmaxf(r, 0.0f), c2wv, c2bv);
            float a = fabsf(r);
            float m = (__expf(a * LN256) - 1.0f) * (1.0f / 255.0f);
            float v = copysignf(m, r);
            out[base + g] = v;
            lmax = fmaxf(lmax, v);
        }
    }

    // block max reduce (reuse smem; all prior smem traffic fenced by last layer's barrier)
    float* red = sh;
    red[tid] = lmax;
    __syncthreads();
    #pragma unroll
    for (int off = NTH / 2; off > 0; off >>= 1) {
        if (tid < off) red[tid] = fmaxf(red[tid], red[tid + off]);
        __syncthreads();
    }
    if (tid == 0) g_tilemax[b * NTILES + tile] = red[0];
}

// per-batch max over tile maxes; also zero the sum accumulator
__global__ void wavenet_k2()
{
    __shared__ float r[64];
    int b = blockIdx.x, tid = threadIdx.x;
    float m = -3.402823466e38f;
    for (int t = tid; t < NTILES; t += 64) m = fmaxf(m, g_tilemax[b * NTILES + t]);
    r[tid] = m;
    __syncthreads();
    #pragma unroll
    for (int off = 32; off > 0; off >>= 1) {
        if (tid < off) r[tid] = fmaxf(r[tid], r[tid + off]);
        __syncthreads();
    }
    if (tid == 0) { g_bmax[b] = r[0]; g_sum[b] = 0.0f; }
}

// exp(v - max) in place + per-batch sum via block partials + atomicAdd
__global__ void wavenet_k3(float* __restrict__ out)
{
    __shared__ float r[256];
    int b = blockIdx.y, tid = threadIdx.x;
    long long off = (long long)b * T_LEN + (long long)blockIdx.x * 2048;
    float bm = g_bmax[b];
    float4* o4 = (float4*)(out + off);
    float ls = 0.0f;
    #pragma unroll
    for (int q = 0; q < 2; q++) {
        int idx = tid + q * 256;
        float4 v = o4[idx];
        v.x = __expf(v.x - bm); v.y = __expf(v.y - bm);
        v.z = __expf(v.z - bm); v.w = __expf(v.w - bm);
        o4[idx] = v;
        ls += (v.x + v.y) + (v.z + v.w);
    }
    r[tid] = ls;
    __syncthreads();
    #pragma unroll
    for (int s = 128; s > 0; s >>= 1) {
        if (tid < s) r[tid] += r[tid + s];
        __syncthreads();
    }
    if (tid == 0) atomicAdd(&g_sum[b], r[0]);
}

// normalize
__global__ void wavenet_k5(float* __restrict__ out)
{
    int b = blockIdx.y, tid = threadIdx.x;
    long long off = (long long)b * T_LEN + (long long)blockIdx.x * 2048;
    float inv = 1.0f / g_sum[b];
    float4* o4 = (float4*)(out + off);
    #pragma unroll
    for (int q = 0; q < 2; q++) {
        int idx = tid + q * 256;
        float4 v = o4[idx];
        v.x *= inv; v.y *= inv; v.z *= inv; v.w *= inv;
        o4[idx] = v;
    }
}

extern "C" void kernel_launch(void* const* d_in, const int* in_sizes, int n_in,
                              void* d_out, int out_size)
{
    const float* x   = (const float*)d_in[0];
    const float* cw  = (const float*)d_in[1];
    const float* cb  = (const float*)d_in[2];
    const float* fw  = (const float*)d_in[3];
    const float* fb  = (const float*)d_in[4];
    const float* gw  = (const float*)d_in[5];
    const float* gb  = (const float*)d_in[6];
    const float* rw  = (const float*)d_in[7];
    const float* rb  = (const float*)d_in[8];
    const float* c1w = (const float*)d_in[9];
    const float* c1b = (const float*)d_in[10];
    const float* c2w = (const float*)d_in[11];
    const float* c2b = (const float*)d_in[12];
    float* out = (float*)d_out;

    cudaFuncSetAttribute(wavenet_k1, cudaFuncAttributeMaxDynamicSharedMemorySize, SMEM_BYTES);

    wavenet_k1<<<dim3(NTILES, BATCH), NTH, SMEM_BYTES>>>(
        x, cw, cb, fw, fb, gw, gb, rw, rb, c1w, c1b, c2w, c2b, out);
    wavenet_k2<<<BATCH, 64>>>();
    wavenet_k3<<<dim3(T_LEN / 2048, BATCH), 256>>>(out);
    wavenet_k5<<<dim3(T_LEN / 2048, BATCH), 256>>>(out);
}

// round 2
// speedup vs baseline: 1.6323x; 1.6323x over previous
#include <cuda_runtime.h>

#define N_LAYERS 30
#define T_LEN    262144
#define BATCH    8
#define NTH      384
#define NPAIR    10                      // pairs per thread
#define LEXT     7680                    // NTH * 2 * NPAIR, exact
#define HALO     576
#define TILE     (LEXT - HALO)           // 7104
#define NTILES   37                      // ceil(262144 / 7104)
#define PADL     32
#define BUFSZ    (PADL + LEXT)           // 7712 (even -> 8B-aligned pairs)
#define WOFF     (2 * BUFSZ)
#define SMEM_FLOATS (WOFF + 448)
#define SMEM_BYTES  (SMEM_FLOATS * 4)

#define LN256 5.545177444479562f

typedef unsigned long long u64;

__constant__ int c_dil[N_LAYERS] = {1,2,4,8,6,2,4,8,6,2,4,8,6,2,4,8,6,2,4,8,6,2,4,8,6,2,4,8,6,2};

__device__ float g_tilemax[BATCH * NTILES];
__device__ float g_bmax[BATCH];
__device__ float g_sum[BATCH];

__device__ __forceinline__ u64 pk(float lo, float hi) {
    u64 r; asm("mov.b64 %0,{%1,%2};" : "=l"(r) : "f"(lo), "f"(hi)); return r;
}
__device__ __forceinline__ void upk(u64 v, float& lo, float& hi) {
    asm("mov.b64 {%0,%1},%2;" : "=f"(lo), "=f"(hi) : "l"(v));
}
__device__ __forceinline__ u64 fma2(u64 a, u64 b, u64 c) {
    u64 d; asm("fma.rn.f32x2 %0,%1,%2,%3;" : "=l"(d) : "l"(a), "l"(b), "l"(c)); return d;
}
__device__ __forceinline__ u64 mul2(u64 a, u64 b) {
    u64 d; asm("mul.rn.f32x2 %0,%1,%2;" : "=l"(d) : "l"(a), "l"(b)); return d;
}
__device__ __forceinline__ u64 add2(u64 a, u64 b) {
    u64 d; asm("add.rn.f32x2 %0,%1,%2;" : "=l"(d) : "l"(a), "l"(b)); return d;
}
__device__ __forceinline__ float tanhap(float x) {
    float y; asm("tanh.approx.f32 %0,%1;" : "=f"(y) : "f"(x)); return y;
}
__device__ __forceinline__ u64 tanh2(u64 v) {
    float a, b; upk(v, a, b);
    return pk(tanhap(a), tanhap(b));
}

__global__ __launch_bounds__(NTH, 2)
void wavenet_k1(const float* __restrict__ x,
                const float* __restrict__ cw,  const float* __restrict__ cb,
                const float* __restrict__ fw,  const float* __restrict__ fb,
                const float* __restrict__ gw,  const float* __restrict__ gb,
                const float* __restrict__ rw,  const float* __restrict__ rb,
                const float* __restrict__ c1w, const float* __restrict__ c1b,
                const float* __restrict__ c2w, const float* __restrict__ c2b,
                float* __restrict__ out)
{
    extern __shared__ float sh[];
    float* buf0 = sh;
    float* buf1 = sh + BUFSZ;
    float* ws   = sh + WOFF;

    const int tid  = threadIdx.x;
    const int tile = blockIdx.x;
    const int b    = blockIdx.y;
    const long long base = (long long)b * T_LEN;
    const int g0 = tile * TILE - HALO;
    const bool zh = (tile == 0);

    // ---- weights -> smem (layout same as round 1) ----
    if (tid < 5)  ws[tid] = cw[tid];
    if (tid == 5) ws[5]   = cb[0];
    for (int j = tid; j < 150; j += NTH) { ws[8 + j] = fw[j]; ws[188 + j] = gw[j]; }
    for (int j = tid; j < 30;  j += NTH) {
        ws[158 + j] = fb[j]; ws[338 + j] = gb[j];
        ws[368 + j] = rw[j]; ws[398 + j] = rb[j];
    }
    if (tid == 0) { ws[428] = c1w[0]; ws[429] = c1b[0]; ws[430] = c2w[0]; ws[431] = c2b[0]; }

    if (tid < PADL) { buf0[tid] = 0.0f; buf1[tid] = 0.0f; }

    // ---- stage x into buf0 (pairs) ----
    #pragma unroll
    for (int p = 0; p < NPAIR; p++) {
        int i = 2 * (tid + p * NTH);
        int g = g0 + i;
        float2 v;
        if (g >= 0 && g + 1 < T_LEN) {
            v = *(const float2*)(x + base + g);
        } else {
            v.x = (g     >= 0 && g     < T_LEN) ? x[base + g]     : 0.0f;
            v.y = (g + 1 >= 0 && g + 1 < T_LEN) ? x[base + g + 1] : 0.0f;
        }
        *(float2*)(buf0 + PADL + i) = v;
    }
    __syncthreads();

    const u64 half2 = pk(0.5f, 0.5f);
    u64 hreg[NPAIR];
    u64 sreg[NPAIR];

    // ---- causal conv (d=1): buf0 -> buf1 + hreg ----
    {
        const float w0 = ws[0], w1 = ws[1], w2 = ws[2], w3 = ws[3], w4 = ws[4];
        const u64 w02 = pk(w0,w0), w12 = pk(w1,w1), w22 = pk(w2,w2),
                  w32 = pk(w3,w3), w42 = pk(w4,w4), bc2 = pk(ws[5], ws[5]);
        #pragma unroll
        for (int p = 0; p < NPAIR; p++) {
            int i = 2 * (tid + p * NTH);
            const float* s = buf0 + PADL + i;
            float m4, m3, m2, m1, h0, h1;
            u64 a  = *(const u64*)(s - 4);
            u64 bb = *(const u64*)(s - 2);
            u64 t0 = *(const u64*)(s);
            upk(a, m4, m3); upk(bb, m2, m1); upk(t0, h0, h1);
            u64 t1 = pk(m1, h0), t2 = pk(m2, m1), t3 = pk(m3, m2), t4 = pk(m4, m3);
            u64 v = fma2(w42, t0,
                    fma2(w32, t1,
                    fma2(w22, t2,
                    fma2(w12, t3,
                    fma2(w02, t4, bc2)))));
            if (zh && i < HALO) v = 0ULL;
            hreg[p] = v;
            sreg[p] = 0ULL;
            *(u64*)(buf1 + PADL + i) = v;
        }
    }
    __syncthreads();

    float* cur = buf1;
    float* nxt = buf0;

    // ---- layer 0 (d=1, odd stride: gather via aligned pairs) ----
    {
        const int k = 0;
        const u64 fw0 = pk(ws[8+5*k],  ws[8+5*k]),  fw1 = pk(ws[9+5*k],  ws[9+5*k]);
        const u64 fw2 = pk(ws[10+5*k], ws[10+5*k]), fw3 = pk(ws[11+5*k], ws[11+5*k]);
        const u64 fw4 = pk(ws[12+5*k], ws[12+5*k]);
        const u64 gw0 = pk(ws[188+5*k], ws[188+5*k]), gw1 = pk(ws[189+5*k], ws[189+5*k]);
        const u64 gw2 = pk(ws[190+5*k], ws[190+5*k]), gw3 = pk(ws[191+5*k], ws[191+5*k]);
        const u64 gw4 = pk(ws[192+5*k], ws[192+5*k]);
        const u64 fb2 = pk(ws[158+k], ws[158+k]), gb2 = pk(ws[338+k], ws[338+k]);
        const u64 rw2 = pk(ws[368+k], ws[368+k]), rb2 = pk(ws[398+k], ws[398+k]);
        #pragma unroll
        for (int p = 0; p < NPAIR; p++) {
            int i = 2 * (tid + p * NTH);
            const float* s = cur + PADL + i;
            float m4, m3, m2, m1, h0, h1;
            u64 a  = *(const u64*)(s - 4);
            u64 bb = *(const u64*)(s - 2);
            u64 t0 = hreg[p];
            upk(a, m4, m3); upk(bb, m2, m1); upk(t0, h0, h1);
            u64 t1 = pk(m1, h0), t2 = pk(m2, m1), t3 = pk(m3, m2), t4 = pk(m4, m3);

            u64 fp = fma2(fw4, t0, fma2(fw3, t1, fma2(fw2, t2, fma2(fw1, t3, fma2(fw0, t4, fb2)))));
            u64 gp = fma2(gw4, t0, fma2(gw3, t1, fma2(gw2, t2, fma2(gw1, t3, fma2(gw0, t4, gb2)))));

            u64 f2v = tanh2(fp);
            u64 g2v = fma2(tanh2(mul2(gp, half2)), half2, half2);
            u64 z   = mul2(f2v, g2v);
            sreg[p] = add2(sreg[p], z);
            u64 hn  = fma2(z, rw2, add2(t0, rb2));
            if (zh && i < HALO) hn = 0ULL;
            hreg[p] = hn;
            *(u64*)(nxt + PADL + i) = hn;
        }
        __syncthreads();
        float* tmp = cur; cur = nxt; nxt = tmp;
    }

    // ---- layers 1..29 (all even dilation: direct 64-bit tap loads) ----
    for (int k = 1; k < N_LAYERS; k++) {
        const int d = c_dil[k];
        const u64 fw0 = pk(ws[8+5*k],  ws[8+5*k]),  fw1 = pk(ws[9+5*k],  ws[9+5*k]);
        const u64 fw2 = pk(ws[10+5*k], ws[10+5*k]), fw3 = pk(ws[11+5*k], ws[11+5*k]);
        const u64 fw4 = pk(ws[12+5*k], ws[12+5*k]);
        const u64 gw0 = pk(ws[188+5*k], ws[188+5*k]), gw1 = pk(ws[189+5*k], ws[189+5*k]);
        const u64 gw2 = pk(ws[190+5*k], ws[190+5*k]), gw3 = pk(ws[191+5*k], ws[191+5*k]);
        const u64 gw4 = pk(ws[192+5*k], ws[192+5*k]);
        const u64 fb2 = pk(ws[158+k], ws[158+k]), gb2 = pk(ws[338+k], ws[338+k]);
        const u64 rw2 = pk(ws[368+k], ws[368+k]), rb2 = pk(ws[398+k], ws[398+k]);

        #pragma unroll
        for (int p = 0; p < NPAIR; p++) {
            int i = 2 * (tid + p * NTH);
            const float* s = cur + PADL + i;
            u64 t1 = *(const u64*)(s - d);
            u64 t2 = *(const u64*)(s - 2*d);
            u64 t3 = *(const u64*)(s - 3*d);
            u64 t4 = *(const u64*)(s - 4*d);
            u64 t0 = hreg[p];

            u64 fp = fma2(fw4, t0, fma2(fw3, t1, fma2(fw2, t2, fma2(fw1, t3, fma2(fw0, t4, fb2)))));
            u64 gp = fma2(gw4, t0, fma2(gw3, t1, fma2(gw2, t2, fma2(gw1, t3, fma2(gw0, t4, gb2)))));

            u64 f2v = tanh2(fp);
            u64 g2v = fma2(tanh2(mul2(gp, half2)), half2, half2);
            u64 z   = mul2(f2v, g2v);
            sreg[p] = add2(sreg[p], z);
            u64 hn  = fma2(z, rw2, add2(t0, rb2));
            if (zh && i < HALO) hn = 0ULL;
            hreg[p] = hn;
            *(u64*)(nxt + PADL + i) = hn;
        }
        __syncthreads();
        float* tmp = cur; cur = nxt; nxt = tmp;
    }

    // ---- epilogue: 1x1 convs + mu-law; write v; track tile max ----
    const float c1wv = ws[428], c1bv = ws[429], c2wv = ws[430], c2bv = ws[431];
    float lmax = -3.402823466e38f;
    #pragma unroll
    for (int p = 0; p < NPAIR; p++) {
        int i = 2 * (tid + p * NTH);
        int g = g0 + i;
        if (i >= HALO) {
            float s0, s1;
            upk(sreg[p], s0, s1);
            float r0 = fmaf(fmaxf(s0, 0.0f), c1wv, c1bv);
            r0 = fmaf(fmaxf(r0, 0.0f), c2wv, c2bv);
            float v0 = copysignf((__expf(fabsf(r0) * LN256) - 1.0f) * (1.0f / 255.0f), r0);
            float r1 = fmaf(fmaxf(s1, 0.0f), c1wv, c1bv);
            r1 = fmaf(fmaxf(r1, 0.0f), c2wv, c2bv);
            float v1 = copysignf((__expf(fabsf(r1) * LN256) - 1.0f) * (1.0f / 255.0f), r1);
            if (g + 1 < T_LEN) {
                *(float2*)(out + base + g) = make_float2(v0, v1);
                lmax = fmaxf(lmax, fmaxf(v0, v1));
            } else if (g < T_LEN) {
                out[base + g] = v0;
                lmax = fmaxf(lmax, v0);
            }
        }
    }

    // block max reduce (smem reuse; fenced by last layer barrier)
    float* red = sh;
    red[tid] = lmax;
    __syncthreads();
    if (tid < 128) red[tid] = fmaxf(fmaxf(red[tid], red[tid + 128]), red[tid + 256]);
    __syncthreads();
    #pragma unroll
    for (int off = 64; off > 0; off >>= 1) {
        if (tid < off) red[tid] = fmaxf(red[tid], red[tid + off]);
        __syncthreads();
    }
    if (tid == 0) g_tilemax[b * NTILES + tile] = red[0];
}

__global__ void wavenet_k2()
{
    __shared__ float r[64];
    int b = blockIdx.x, tid = threadIdx.x;
    float m = -3.402823466e38f;
    for (int t = tid; t < NTILES; t += 64) m = fmaxf(m, g_tilemax[b * NTILES + t]);
    r[tid] = m;
    __syncthreads();
    #pragma unroll
    for (int off = 32; off > 0; off >>= 1) {
        if (tid < off) r[tid] = fmaxf(r[tid], r[tid + off]);
        __syncthreads();
    }
    if (tid == 0) { g_bmax[b] = r[0]; g_sum[b] = 0.0f; }
}

__global__ void wavenet_k3(float* __restrict__ out)
{
    __shared__ float r[256];
    int b = blockIdx.y, tid = threadIdx.x;
    long long off = (long long)b * T_LEN + (long long)blockIdx.x * 2048;
    float bm = g_bmax[b];
    float4* o4 = (float4*)(out + off);
    float ls = 0.0f;
    #pragma unroll
    for (int q = 0; q < 2; q++) {
        int idx = tid + q * 256;
        float4 v = o4[idx];
        v.x = __expf(v.x - bm); v.y = __expf(v.y - bm);
        v.z = __expf(v.z - bm); v.w = __expf(v.w - bm);
        o4[idx] = v;
        ls += (v.x + v.y) + (v.z + v.w);
    }
    r[tid] = ls;
    __syncthreads();
    #pragma unroll
    for (int s = 128; s > 0; s >>= 1) {
        if (tid < s) r[tid] += r[tid + s];
        __syncthreads();
    }
    if (tid == 0) atomicAdd(&g_sum[b], r[0]);
}

__global__ void wavenet_k5(float* __restrict__ out)
{
    int b = blockIdx.y, tid = threadIdx.x;
    long long off = (long long)b * T_LEN + (long long)blockIdx.x * 2048;
    float inv = 1.0f / g_sum[b];
    float4* o4 = (float4*)(out + off);
    #pragma unroll
    for (int q = 0; q < 2; q++) {
        int idx = tid + q * 256;
        float4 v = o4[idx];
        v.x *= inv; v.y *= inv; v.z *= inv; v.w *= inv;
        o4[idx] = v;
    }
}

extern "C" void kernel_launch(void* const* d_in, const int* in_sizes, int n_in,
                              void* d_out, int out_size)
{
    const float* x   = (const float*)d_in[0];
    const float* cw  = (const float*)d_in[1];
    const float* cb  = (const float*)d_in[2];
    const float* fw  = (const float*)d_in[3];
    const float* fb  = (const float*)d_in[4];
    const float* gw  = (const float*)d_in[5];
    const float* gb  = (const float*)d_in[6];
    const float* rw  = (const float*)d_in[7];
    const float* rb  = (const float*)d_in[8];
    const float* c1w = (const float*)d_in[9];
    const float* c1b = (const float*)d_in[10];
    const float* c2w = (const float*)d_in[11];
    const float* c2b = (const float*)d_in[12];
    float* out = (float*)d_out;

    cudaFuncSetAttribute(wavenet_k1, cudaFuncAttributeMaxDynamicSharedMemorySize, SMEM_BYTES);

    wavenet_k1<<<dim3(NTILES, BATCH), NTH, SMEM_BYTES>>>(
        x, cw, cb, fw, fb, gw, gb, rw, rb, c1w, c1b, c2w, c2b, out);
    wavenet_k2<<<BATCH, 64>>>();
    wavenet_k3<<<dim3(T_LEN / 2048, BATCH), 256>>>(out);
    wavenet_k5<<<dim3(T_LEN / 2048, BATCH), 256>>>(out);
}

// round 3
// speedup vs baseline: 1.7465x; 1.0699x over previous
#include <cuda_runtime.h>

#define N_LAYERS 30
#define T_LEN    262144
#define BATCH    8
#define NTH      384
#define NPAIR    10                      // pairs per thread
#define LEXT     7680                    // NTH * 2 * NPAIR, exact
#define HALO     576
#define TILE     (LEXT - HALO)           // 7104
#define NTILES   37                      // ceil(262144 / 7104)
#define PADL     32
#define BUFSZ    (PADL + LEXT)           // 7712
#define WOFF     (2 * BUFSZ)
#define SMEM_FLOATS (WOFF + 448)
#define SMEM_BYTES  (SMEM_FLOATS * 4)

#define LN256  5.545177444479562f
#define NEGBIG -3.402823466e38f

typedef unsigned long long u64;

__constant__ int c_dil[N_LAYERS] = {1,2,4,8,6,2,4,8,6,2,4,8,6,2,4,8,6,2,4,8,6,2,4,8,6,2,4,8,6,2};

__device__ float g_tilemax[BATCH * NTILES];
__device__ float g_tilesum[BATCH * NTILES];
__device__ float g_bmax[BATCH];
__device__ float g_inv[BATCH];

__device__ __forceinline__ u64 pk(float lo, float hi) {
    u64 r; asm("mov.b64 %0,{%1,%2};" : "=l"(r) : "f"(lo), "f"(hi)); return r;
}
__device__ __forceinline__ void upk(u64 v, float& lo, float& hi) {
    asm("mov.b64 {%0,%1},%2;" : "=f"(lo), "=f"(hi) : "l"(v));
}
__device__ __forceinline__ u64 fma2(u64 a, u64 b, u64 c) {
    u64 d; asm("fma.rn.f32x2 %0,%1,%2,%3;" : "=l"(d) : "l"(a), "l"(b), "l"(c)); return d;
}
__device__ __forceinline__ u64 mul2(u64 a, u64 b) {
    u64 d; asm("mul.rn.f32x2 %0,%1,%2;" : "=l"(d) : "l"(a), "l"(b)); return d;
}
__device__ __forceinline__ u64 add2(u64 a, u64 b) {
    u64 d; asm("add.rn.f32x2 %0,%1,%2;" : "=l"(d) : "l"(a), "l"(b)); return d;
}
__device__ __forceinline__ float tanhap(float x) {
    float y; asm("tanh.approx.f32 %0,%1;" : "=f"(y) : "f"(x)); return y;
}
__device__ __forceinline__ u64 tanh2(u64 v) {
    float a, b; upk(v, a, b);
    return pk(tanhap(a), tanhap(b));
}

__global__ __launch_bounds__(NTH, 2)
void wavenet_k1(const float* __restrict__ x,
                const float* __restrict__ cw,  const float* __restrict__ cb,
                const float* __restrict__ fw,  const float* __restrict__ fb,
                const float* __restrict__ gw,  const float* __restrict__ gb,
                const float* __restrict__ rw,  const float* __restrict__ rb,
                const float* __restrict__ c1w, const float* __restrict__ c1b,
                const float* __restrict__ c2w, const float* __restrict__ c2b,
                float* __restrict__ out)
{
    extern __shared__ float sh[];
    float* buf0 = sh;
    float* buf1 = sh + BUFSZ;
    float* ws   = sh + WOFF;

    const int tid  = threadIdx.x;
    const int tile = blockIdx.x;
    const int b    = blockIdx.y;
    const long long base = (long long)b * T_LEN;
    const int g0 = tile * TILE - HALO;
    const bool zh = (tile == 0);

    // ---- weights -> smem. Gate weights/bias pre-scaled by 0.5 (exact). ----
    if (tid < 5)  ws[tid] = cw[tid];
    if (tid == 5) ws[5]   = cb[0];
    for (int j = tid; j < 150; j += NTH) { ws[8 + j] = fw[j]; ws[188 + j] = gw[j] * 0.5f; }
    for (int j = tid; j < 30;  j += NTH) {
        ws[158 + j] = fb[j]; ws[338 + j] = gb[j] * 0.5f;
        ws[368 + j] = rw[j]; ws[398 + j] = rb[j];
    }
    if (tid == 0) { ws[428] = c1w[0]; ws[429] = c1b[0]; ws[430] = c2w[0]; ws[431] = c2b[0]; }

    if (tid < PADL) { buf0[tid] = 0.0f; buf1[tid] = 0.0f; }

    // ---- stage x into buf0 (pairs) ----
    #pragma unroll
    for (int p = 0; p < NPAIR; p++) {
        int i = 2 * (tid + p * NTH);
        int g = g0 + i;
        float2 v;
        if (g >= 0 && g + 1 < T_LEN) {
            v = *(const float2*)(x + base + g);
        } else {
            v.x = (g     >= 0 && g     < T_LEN) ? x[base + g]     : 0.0f;
            v.y = (g + 1 >= 0 && g + 1 < T_LEN) ? x[base + g + 1] : 0.0f;
        }
        *(float2*)(buf0 + PADL + i) = v;
    }
    __syncthreads();

    const u64 half2 = pk(0.5f, 0.5f);
    u64 hreg[NPAIR];
    u64 sreg[NPAIR];

    // ---- causal conv (d=1): buf0 -> buf1 + hreg ----
    {
        const float w0 = ws[0], w1 = ws[1], w2 = ws[2], w3 = ws[3], w4 = ws[4];
        const u64 w02 = pk(w0,w0), w12 = pk(w1,w1), w22 = pk(w2,w2),
                  w32 = pk(w3,w3), w42 = pk(w4,w4), bc2 = pk(ws[5], ws[5]);
        #pragma unroll
        for (int p = 0; p < NPAIR; p++) {
            int i = 2 * (tid + p * NTH);
            const float* s = buf0 + PADL + i;
            float m4, m3, m2, m1, h0, h1;
            u64 a  = *(const u64*)(s - 4);
            u64 bb = *(const u64*)(s - 2);
            u64 t0 = *(const u64*)(s);
            upk(a, m4, m3); upk(bb, m2, m1); upk(t0, h0, h1);
            u64 t1 = pk(m1, h0), t2 = pk(m2, m1), t3 = pk(m3, m2), t4 = pk(m4, m3);
            u64 v = fma2(w42, t0,
                    fma2(w32, t1,
                    fma2(w22, t2,
                    fma2(w12, t3,
                    fma2(w02, t4, bc2)))));
            if (zh && i < HALO) v = 0ULL;
            hreg[p] = v;
            sreg[p] = 0ULL;
            *(u64*)(buf1 + PADL + i) = v;
        }
    }
    __syncthreads();

    float* cur = buf1;
    float* nxt = buf0;

    // ---- layer 0 (d=1, odd stride: gather via aligned pairs) ----
    {
        const int k = 0;
        const u64 fw0 = pk(ws[8+5*k],  ws[8+5*k]),  fw1 = pk(ws[9+5*k],  ws[9+5*k]);
        const u64 fw2 = pk(ws[10+5*k], ws[10+5*k]), fw3 = pk(ws[11+5*k], ws[11+5*k]);
        const u64 fw4 = pk(ws[12+5*k], ws[12+5*k]);
        const u64 gw0 = pk(ws[188+5*k], ws[188+5*k]), gw1 = pk(ws[189+5*k], ws[189+5*k]);
        const u64 gw2 = pk(ws[190+5*k], ws[190+5*k]), gw3 = pk(ws[191+5*k], ws[191+5*k]);
        const u64 gw4 = pk(ws[192+5*k], ws[192+5*k]);
        const u64 fb2 = pk(ws[158+k], ws[158+k]), gb2 = pk(ws[338+k], ws[338+k]);
        const u64 rw2 = pk(ws[368+k], ws[368+k]), rb2 = pk(ws[398+k], ws[398+k]);
        #pragma unroll
        for (int p = 0; p < NPAIR; p++) {
            int i = 2 * (tid + p * NTH);
            const float* s = cur + PADL + i;
            float m4, m3, m2, m1, h0, h1;
            u64 a  = *(const u64*)(s - 4);
            u64 bb = *(const u64*)(s - 2);
            u64 t0 = hreg[p];
            upk(a, m4, m3); upk(bb, m2, m1); upk(t0, h0, h1);
            u64 t1 = pk(m1, h0), t2 = pk(m2, m1), t3 = pk(m3, m2), t4 = pk(m4, m3);

            u64 fp = fma2(fw4, t0, fma2(fw3, t1, fma2(fw2, t2, fma2(fw1, t3, fma2(fw0, t4, fb2)))));
            u64 gp = fma2(gw4, t0, fma2(gw3, t1, fma2(gw2, t2, fma2(gw1, t3, fma2(gw0, t4, gb2)))));

            u64 f2v = tanh2(fp);
            u64 g2v = fma2(tanh2(gp), half2, half2);
            u64 z   = mul2(f2v, g2v);
            sreg[p] = add2(sreg[p], z);
            u64 hn  = fma2(z, rw2, add2(t0, rb2));
            if (zh && i < HALO) hn = 0ULL;
            hreg[p] = hn;
            *(u64*)(nxt + PADL + i) = hn;
        }
        __syncthreads();
        float* tmp = cur; cur = nxt; nxt = tmp;
    }

    // ---- layers 1..28 (even dilation: direct 64-bit tap loads) ----
    for (int k = 1; k < N_LAYERS - 1; k++) {
        const int d = c_dil[k];
        const u64 fw0 = pk(ws[8+5*k],  ws[8+5*k]),  fw1 = pk(ws[9+5*k],  ws[9+5*k]);
        const u64 fw2 = pk(ws[10+5*k], ws[10+5*k]), fw3 = pk(ws[11+5*k], ws[11+5*k]);
        const u64 fw4 = pk(ws[12+5*k], ws[12+5*k]);
        const u64 gw0 = pk(ws[188+5*k], ws[188+5*k]), gw1 = pk(ws[189+5*k], ws[189+5*k]);
        const u64 gw2 = pk(ws[190+5*k], ws[190+5*k]), gw3 = pk(ws[191+5*k], ws[191+5*k]);
        const u64 gw4 = pk(ws[192+5*k], ws[192+5*k]);
        const u64 fb2 = pk(ws[158+k], ws[158+k]), gb2 = pk(ws[338+k], ws[338+k]);
        const u64 rw2 = pk(ws[368+k], ws[368+k]), rb2 = pk(ws[398+k], ws[398+k]);

        #pragma unroll
        for (int p = 0; p < NPAIR; p++) {
            int i = 2 * (tid + p * NTH);
            const float* s = cur + PADL + i;
            u64 t1 = *(const u64*)(s - d);
            u64 t2 = *(const u64*)(s - 2*d);
            u64 t3 = *(const u64*)(s - 3*d);
            u64 t4 = *(const u64*)(s - 4*d);
            u64 t0 = hreg[p];

            u64 fp = fma2(fw4, t0, fma2(fw3, t1, fma2(fw2, t2, fma2(fw1, t3, fma2(fw0, t4, fb2)))));
            u64 gp = fma2(gw4, t0, fma2(gw3, t1, fma2(gw2, t2, fma2(gw1, t3, fma2(gw0, t4, gb2)))));

            u64 f2v = tanh2(fp);
            u64 g2v = fma2(tanh2(gp), half2, half2);
            u64 z   = mul2(f2v, g2v);
            sreg[p] = add2(sreg[p], z);
            u64 hn  = fma2(z, rw2, add2(t0, rb2));
            if (zh && i < HALO) hn = 0ULL;
            hreg[p] = hn;
            *(u64*)(nxt + PADL + i) = hn;
        }
        __syncthreads();
        float* tmp = cur; cur = nxt; nxt = tmp;
    }

    // ---- layer 29: skips only — no h write, no barrier ----
    {
        const int k = N_LAYERS - 1;
        const int d = c_dil[k];
        const u64 fw0 = pk(ws[8+5*k],  ws[8+5*k]),  fw1 = pk(ws[9+5*k],  ws[9+5*k]);
        const u64 fw2 = pk(ws[10+5*k], ws[10+5*k]), fw3 = pk(ws[11+5*k], ws[11+5*k]);
        const u64 fw4 = pk(ws[12+5*k], ws[12+5*k]);
        const u64 gw0 = pk(ws[188+5*k], ws[188+5*k]), gw1 = pk(ws[189+5*k], ws[189+5*k]);
        const u64 gw2 = pk(ws[190+5*k], ws[190+5*k]), gw3 = pk(ws[191+5*k], ws[191+5*k]);
        const u64 gw4 = pk(ws[192+5*k], ws[192+5*k]);
        const u64 fb2 = pk(ws[158+k], ws[158+k]), gb2 = pk(ws[338+k], ws[338+k]);

        #pragma unroll
        for (int p = 0; p < NPAIR; p++) {
            int i = 2 * (tid + p * NTH);
            const float* s = cur + PADL + i;
            u64 t1 = *(const u64*)(s - d);
            u64 t2 = *(const u64*)(s - 2*d);
            u64 t3 = *(const u64*)(s - 3*d);
            u64 t4 = *(const u64*)(s - 4*d);
            u64 t0 = hreg[p];

            u64 fp = fma2(fw4, t0, fma2(fw3, t1, fma2(fw2, t2, fma2(fw1, t3, fma2(fw0, t4, fb2)))));
            u64 gp = fma2(gw4, t0, fma2(gw3, t1, fma2(gw2, t2, fma2(gw1, t3, fma2(gw0, t4, gb2)))));

            u64 f2v = tanh2(fp);
            u64 g2v = fma2(tanh2(gp), half2, half2);
            u64 z   = mul2(f2v, g2v);
            sreg[p] = add2(sreg[p], z);
        }
    }

    // ---- epilogue: 1x1 convs + mu-law; write v; keep v in sreg ----
    const float c1wv = ws[428], c1bv = ws[429], c2wv = ws[430], c2bv = ws[431];
    float lmax = NEGBIG;
    #pragma unroll
    for (int p = 0; p < NPAIR; p++) {
        int i = 2 * (tid + p * NTH);
        int g = g0 + i;
        float v0 = NEGBIG, v1 = NEGBIG;
        if (i >= HALO) {
            float s0, s1;
            upk(sreg[p], s0, s1);
            float r0 = fmaf(fmaxf(s0, 0.0f), c1wv, c1bv);
            r0 = fmaf(fmaxf(r0, 0.0f), c2wv, c2bv);
            float w0 = copysignf((__expf(fabsf(r0) * LN256) - 1.0f) * (1.0f / 255.0f), r0);
            float r1 = fmaf(fmaxf(s1, 0.0f), c1wv, c1bv);
            r1 = fmaf(fmaxf(r1, 0.0f), c2wv, c2bv);
            float w1 = copysignf((__expf(fabsf(r1) * LN256) - 1.0f) * (1.0f / 255.0f), r1);
            if (g + 1 < T_LEN) {
                *(float2*)(out + base + g) = make_float2(w0, w1);
                v0 = w0; v1 = w1;
            } else if (g < T_LEN) {
                out[base + g] = w0;
                v0 = w0;
            }
        }
        sreg[p] = pk(v0, v1);
        lmax = fmaxf(lmax, fmaxf(v0, v1));
    }

    // ---- block max reduce (barrier first: smem may still be read by layer 29) ----
    __syncthreads();
    float* red = sh;
    red[tid] = lmax;
    __syncthreads();
    if (tid < 128) red[tid] = fmaxf(fmaxf(red[tid], red[tid + 128]), red[tid + 256]);
    __syncthreads();
    #pragma unroll
    for (int off = 64; off > 0; off >>= 1) {
        if (tid < off) red[tid] = fmaxf(red[tid], red[tid + off]);
        __syncthreads();
    }
    const float tmax = red[0];
    __syncthreads();

    // ---- per-tile exp-sum (invalid lanes are -FLT_MAX -> exp underflows to 0) ----
    float lsum = 0.0f;
    #pragma unroll
    for (int p = 0; p < NPAIR; p++) {
        float v0, v1;
        upk(sreg[p], v0, v1);
        lsum += __expf(v0 - tmax) + __expf(v1 - tmax);
    }
    red[tid] = lsum;
    __syncthreads();
    if (tid < 128) red[tid] = red[tid] + red[tid + 128] + red[tid + 256];
    __syncthreads();
    #pragma unroll
    for (int off = 64; off > 0; off >>= 1) {
        if (tid < off) red[tid] = red[tid] + red[tid + off];
        __syncthreads();
    }
    if (tid == 0) {
        g_tilemax[b * NTILES + tile] = tmax;
        g_tilesum[b * NTILES + tile] = red[0];
    }
}

// per-batch: combine tile (max, sum) -> bmax, 1/sum
__global__ void wavenet_k2()
{
    __shared__ float rm[64];
    __shared__ float rs[64];
    int b = blockIdx.x, tid = threadIdx.x;
    float m = NEGBIG, s = 0.0f;
    if (tid < NTILES) { m = g_tilemax[b * NTILES + tid]; s = g_tilesum[b * NTILES + tid]; }
    rm[tid] = m;
    __syncthreads();
    #pragma unroll
    for (int off = 32; off > 0; off >>= 1) {
        if (tid < off) rm[tid] = fmaxf(rm[tid], rm[tid + off]);
        __syncthreads();
    }
    float bmax = rm[0];
    rs[tid] = s * __expf(m - bmax);   // m=-inf lanes give 0
    __syncthreads();
    #pragma unroll
    for (int off = 32; off > 0; off >>= 1) {
        if (tid < off) rs[tid] = rs[tid] + rs[tid + off];
        __syncthreads();
    }
    if (tid == 0) { g_bmax[b] = bmax; g_inv[b] = 1.0f / rs[0]; }
}

// out = exp(v - bmax) * inv  (single RMW pass)
__global__ void wavenet_k5(float* __restrict__ out)
{
    int b = blockIdx.y, tid = threadIdx.x;
    long long off = (long long)b * T_LEN + (long long)blockIdx.x * 2048;
    float bm  = g_bmax[b];
    float inv = g_inv[b];
    float4* o4 = (float4*)(out + off);
    #pragma unroll
    for (int q = 0; q < 2; q++) {
        int idx = tid + q * 256;
        float4 v = o4[idx];
        v.x = __expf(v.x - bm) * inv;
        v.y = __expf(v.y - bm) * inv;
        v.z = __expf(v.z - bm) * inv;
        v.w = __expf(v.w - bm) * inv;
        o4[idx] = v;
    }
}

extern "C" void kernel_launch(void* const* d_in, const int* in_sizes, int n_in,
                              void* d_out, int out_size)
{
    const float* x   = (const float*)d_in[0];
    const float* cw  = (const float*)d_in[1];
    const float* cb  = (const float*)d_in[2];
    const float* fw  = (const float*)d_in[3];
    const float* fb  = (const float*)d_in[4];
    const float* gw  = (const float*)d_in[5];
    const float* gb  = (const float*)d_in[6];
    const float* rw  = (const float*)d_in[7];
    const float* rb  = (const float*)d_in[8];
    const float* c1w = (const float*)d_in[9];
    const float* c1b = (const float*)d_in[10];
    const float* c2w = (const float*)d_in[11];
    const float* c2b = (const float*)d_in[12];
    float* out = (float*)d_out;

    cudaFuncSetAttribute(wavenet_k1, cudaFuncAttributeMaxDynamicSharedMemorySize, SMEM_BYTES);

    wavenet_k1<<<dim3(NTILES, BATCH), NTH, SMEM_BYTES>>>(
        x, cw, cb, fw, fb, gw, gb, rw, rb, c1w, c1b, c2w, c2b, out);
    wavenet_k2<<<BATCH, 64>>>();
    wavenet_k5<<<dim3(T_LEN / 2048, BATCH), 256>>>(out);
}

// round 4
// speedup vs baseline: 1.8557x; 1.0625x over previous
#include <cuda_runtime.h>

#define N_LAYERS 30
#define T_LEN    262144
#define BATCH    8
#define NTH      384
#define NPAIR    10
#define LEXT     7680                    // NTH*2*NPAIR
#define HALO     576
#define TILE     (LEXT - HALO)           // 7104
#define NTILES   37
#define NCTAS    (NTILES * BATCH)        // 296 = 148 SMs x occ 2
#define PADL     32                      // zero-pad samples (max lookback 32)
#define BUFU32   (PADL/2 + LEXT/2)       // 3856 u32 words per bf16 buffer
#define WOFFB    (2 * BUFU32 * 4)        // byte offset of weights
#define SMEM_BYTES (WOFFB + 448 * 4)     // 32640 B

#define LN256  5.545177444479562f
#define NEGBIG -3.402823466e38f

typedef unsigned long long u64;
typedef unsigned int u32;

__device__ float g_tilemax[NCTAS];
__device__ float g_tilesum[NCTAS];
__device__ u32   g_arrive;   // zero-init
__device__ u32   g_epoch;    // zero-init

__device__ __forceinline__ u64 pk(float lo, float hi) {
    u64 r; asm("mov.b64 %0,{%1,%2};" : "=l"(r) : "f"(lo), "f"(hi)); return r;
}
__device__ __forceinline__ void upk(u64 v, float& lo, float& hi) {
    asm("mov.b64 {%0,%1},%2;" : "=f"(lo), "=f"(hi) : "l"(v));
}
__device__ __forceinline__ u64 fma2(u64 a, u64 b, u64 c) {
    u64 d; asm("fma.rn.f32x2 %0,%1,%2,%3;" : "=l"(d) : "l"(a), "l"(b), "l"(c)); return d;
}
__device__ __forceinline__ u64 mul2(u64 a, u64 b) {
    u64 d; asm("mul.rn.f32x2 %0,%1,%2;" : "=l"(d) : "l"(a), "l"(b)); return d;
}
__device__ __forceinline__ u64 add2(u64 a, u64 b) {
    u64 d; asm("add.rn.f32x2 %0,%1,%2;" : "=l"(d) : "l"(a), "l"(b)); return d;
}
__device__ __forceinline__ float tanhap(float x) {
    float y; asm("tanh.approx.f32 %0,%1;" : "=f"(y) : "f"(x)); return y;
}
__device__ __forceinline__ u64 tanh2(u64 v) {
    float a, b; upk(v, a, b);
    return pk(tanhap(a), tanhap(b));
}
// bf16x2 word -> f32x2 (exact: bf16 is top 16 bits of f32)
__device__ __forceinline__ u64 bx(u32 v) {
    u32 lo = v << 16;
    u32 hi = v & 0xFFFF0000u;
    u64 r; asm("mov.b64 %0,{%1,%2};" : "=l"(r) : "r"(lo), "r"(hi)); return r;
}
// f32x2 -> bf16x2 word (round-to-nearest)
__device__ __forceinline__ u32 cvtb(u64 v) {
    float lo, hi; upk(v, lo, hi);
    u32 r; asm("cvt.rn.bf16x2.f32 %0,%1,%2;" : "=r"(r) : "f"(hi), "f"(lo)); return r;
}
__device__ __forceinline__ u32 cvtb2(float lo, float hi) {
    u32 r; asm("cvt.rn.bf16x2.f32 %0,%1,%2;" : "=r"(r) : "f"(hi), "f"(lo)); return r;
}

// One gated residual layer, dilation D (even, compile-time), bf16 smem taps.
template<int D, bool STORE>
__device__ __forceinline__ void layer_even(int k, const u32* cur, u32* nxt,
                                           const float* ws, int tid, bool zh,
                                           u64* hreg, u64* sreg, u64 half2)
{
    const u64 fw0 = pk(ws[8+5*k],  ws[8+5*k]),  fw1 = pk(ws[9+5*k],  ws[9+5*k]);
    const u64 fw2 = pk(ws[10+5*k], ws[10+5*k]), fw3 = pk(ws[11+5*k], ws[11+5*k]);
    const u64 fw4 = pk(ws[12+5*k], ws[12+5*k]);
    const u64 gw0 = pk(ws[188+5*k], ws[188+5*k]), gw1 = pk(ws[189+5*k], ws[189+5*k]);
    const u64 gw2 = pk(ws[190+5*k], ws[190+5*k]), gw3 = pk(ws[191+5*k], ws[191+5*k]);
    const u64 gw4 = pk(ws[192+5*k], ws[192+5*k]);
    const u64 fb2 = pk(ws[158+k], ws[158+k]), gb2 = pk(ws[338+k], ws[338+k]);
    u64 rw2 = 0, rb2 = 0;
    if (STORE) { rw2 = pk(ws[368+k], ws[368+k]); rb2 = pk(ws[398+k], ws[398+k]); }

    #pragma unroll
    for (int p = 0; p < NPAIR; p++) {
        int q = tid + p * NTH;
        const u32* s = cur + (PADL/2) + q;
        u64 t1 = bx(s[-(D/2)]);
        u64 t2 = bx(s[-D]);
        u64 t3 = bx(s[-(3*D/2)]);
        u64 t4 = bx(s[-(2*D)]);
        u64 t0 = hreg[p];

        u64 fp = fma2(fw4, t0, fma2(fw3, t1, fma2(fw2, t2, fma2(fw1, t3, fma2(fw0, t4, fb2)))));
        u64 gp = fma2(gw4, t0, fma2(gw3, t1, fma2(gw2, t2, fma2(gw1, t3, fma2(gw0, t4, gb2)))));

        u64 f2v = tanh2(fp);
        u64 g2v = fma2(tanh2(gp), half2, half2);   // sigmoid (gate pre-scaled 0.5)
        u64 z   = mul2(f2v, g2v);
        sreg[p] = add2(sreg[p], z);
        if (STORE) {
            u64 hn = fma2(z, rw2, add2(t0, rb2));
            if (zh && 2*q < HALO) hn = 0ULL;
            hreg[p] = hn;
            nxt[(PADL/2) + q] = cvtb(hn);
        }
    }
    if (STORE) __syncthreads();
}

__global__ __launch_bounds__(NTH, 2)
void wavenet_k1(const float* __restrict__ x,
                const float* __restrict__ cw,  const float* __restrict__ cb,
                const float* __restrict__ fw,  const float* __restrict__ fb,
                const float* __restrict__ gw,  const float* __restrict__ gb,
                const float* __restrict__ rw,  const float* __restrict__ rb,
                const float* __restrict__ c1w, const float* __restrict__ c1b,
                const float* __restrict__ c2w, const float* __restrict__ c2b,
                float* __restrict__ out)
{
    extern __shared__ char smem[];
    u32*   b0 = (u32*)smem;
    u32*   b1 = b0 + BUFU32;
    float* ws = (float*)(smem + WOFFB);

    const int tid  = threadIdx.x;
    const int tile = blockIdx.x;
    const int b    = blockIdx.y;
    const long long base = (long long)b * T_LEN;
    const int g0 = tile * TILE - HALO;
    const bool zh = (tile == 0);

    // ---- weights -> smem (gate pre-scaled by 0.5, exact) ----
    if (tid < 5)  ws[tid] = cw[tid];
    if (tid == 5) ws[5]   = cb[0];
    for (int j = tid; j < 150; j += NTH) { ws[8 + j] = fw[j]; ws[188 + j] = gw[j] * 0.5f; }
    for (int j = tid; j < 30;  j += NTH) {
        ws[158 + j] = fb[j]; ws[338 + j] = gb[j] * 0.5f;
        ws[368 + j] = rw[j]; ws[398 + j] = rb[j];
    }
    if (tid == 0) { ws[428] = c1w[0]; ws[429] = c1b[0]; ws[430] = c2w[0]; ws[431] = c2b[0]; }

    if (tid < PADL/2) { b0[tid] = 0u; b1[tid] = 0u; }

    // ---- stage x -> bf16 buf0 ----
    #pragma unroll
    for (int p = 0; p < NPAIR; p++) {
        int q = tid + p * NTH;
        int g = g0 + 2*q;
        float2 v;
        if (g >= 0 && g + 1 < T_LEN) {
            v = *(const float2*)(x + base + g);
        } else {
            v.x = (g     >= 0 && g     < T_LEN) ? x[base + g]     : 0.0f;
            v.y = (g + 1 >= 0 && g + 1 < T_LEN) ? x[base + g + 1] : 0.0f;
        }
        b0[(PADL/2) + q] = cvtb2(v.x, v.y);
    }
    __syncthreads();

    const u64 half2 = pk(0.5f, 0.5f);
    u64 hreg[NPAIR];
    u64 sreg[NPAIR];

    // ---- causal conv (d=1): b0 -> b1 + hreg ----
    {
        const u64 w02 = pk(ws[0],ws[0]), w12 = pk(ws[1],ws[1]), w22 = pk(ws[2],ws[2]),
                  w32 = pk(ws[3],ws[3]), w42 = pk(ws[4],ws[4]), bc2 = pk(ws[5],ws[5]);
        #pragma unroll
        for (int p = 0; p < NPAIR; p++) {
            int q = tid + p * NTH;
            const u32* s = b0 + (PADL/2) + q;
            float m4, m3, m2, m1, h0, h1;
            u64 A = bx(s[-2]), B = bx(s[-1]), t0 = bx(s[0]);
            upk(A, m4, m3); upk(B, m2, m1); upk(t0, h0, h1);
            u64 t1 = pk(m1, h0), t2 = pk(m2, m1), t3 = pk(m3, m2), t4 = pk(m4, m3);
            u64 v = fma2(w42, t0, fma2(w32, t1, fma2(w22, t2, fma2(w12, t3, fma2(w02, t4, bc2)))));
            if (zh && 2*q < HALO) v = 0ULL;
            hreg[p] = v;
            sreg[p] = 0ULL;
            b1[(PADL/2) + q] = cvtb(v);
        }
    }
    __syncthreads();

    u32* cur = b1;
    u32* nxt = b0;

    // ---- layer 0 (d=1): misaligned gather via bf16 words ----
    {
        const int k = 0;
        const u64 fw0 = pk(ws[8],ws[8]),   fw1 = pk(ws[9],ws[9]),   fw2 = pk(ws[10],ws[10]);
        const u64 fw3 = pk(ws[11],ws[11]), fw4 = pk(ws[12],ws[12]);
        const u64 gw0 = pk(ws[188],ws[188]), gw1 = pk(ws[189],ws[189]), gw2 = pk(ws[190],ws[190]);
        const u64 gw3 = pk(ws[191],ws[191]), gw4 = pk(ws[192],ws[192]);
        const u64 fb2 = pk(ws[158],ws[158]), gb2 = pk(ws[338],ws[338]);
        const u64 rw2 = pk(ws[368],ws[368]), rb2 = pk(ws[398],ws[398]);
        (void)k;
        #pragma unroll
        for (int p = 0; p < NPAIR; p++) {
            int q = tid + p * NTH;
            const u32* s = cur + (PADL/2) + q;
            float m4, m3, m2, m1, h0, h1;
            u64 A = bx(s[-2]), B = bx(s[-1]);
            u64 t0 = hreg[p];
            upk(A, m4, m3); upk(B, m2, m1); upk(t0, h0, h1);
            u64 t1 = pk(m1, h0), t2 = pk(m2, m1), t3 = pk(m3, m2), t4 = pk(m4, m3);

            u64 fp = fma2(fw4, t0, fma2(fw3, t1, fma2(fw2, t2, fma2(fw1, t3, fma2(fw0, t4, fb2)))));
            u64 gp = fma2(gw4, t0, fma2(gw3, t1, fma2(gw2, t2, fma2(gw1, t3, fma2(gw0, t4, gb2)))));

            u64 f2v = tanh2(fp);
            u64 g2v = fma2(tanh2(gp), half2, half2);
            u64 z   = mul2(f2v, g2v);
            sreg[p] = add2(sreg[p], z);
            u64 hn  = fma2(z, rw2, add2(t0, rb2));
            if (zh && 2*q < HALO) hn = 0ULL;
            hreg[p] = hn;
            nxt[(PADL/2) + q] = cvtb(hn);
        }
        __syncthreads();
        u32* tmp = cur; cur = nxt; nxt = tmp;
    }

    // ---- layers 1..28: static dilation cycle (2,4,8,6) x 7 ----
    int k = 1;
    #pragma unroll 1
    for (int j = 0; j < 7; j++) {
        layer_even<2, true>(k,   cur, nxt, ws, tid, zh, hreg, sreg, half2);
        { u32* t = cur; cur = nxt; nxt = t; }
        layer_even<4, true>(k+1, cur, nxt, ws, tid, zh, hreg, sreg, half2);
        { u32* t = cur; cur = nxt; nxt = t; }
        layer_even<8, true>(k+2, cur, nxt, ws, tid, zh, hreg, sreg, half2);
        { u32* t = cur; cur = nxt; nxt = t; }
        layer_even<6, true>(k+3, cur, nxt, ws, tid, zh, hreg, sreg, half2);
        { u32* t = cur; cur = nxt; nxt = t; }
        k += 4;
    }
    // ---- layer 29 (d=2): skips only ----
    layer_even<2, false>(29, cur, nxt, ws, tid, zh, hreg, sreg, half2);

    // ---- epilogue: 1x1 convs + mu-law; v kept in sreg ----
    const float c1wv = ws[428], c1bv = ws[429], c2wv = ws[430], c2bv = ws[431];
    float lmax = NEGBIG;
    #pragma unroll
    for (int p = 0; p < NPAIR; p++) {
        int q = tid + p * NTH;
        int i = 2*q;
        int g = g0 + i;
        float v0 = NEGBIG, v1 = NEGBIG;
        if (i >= HALO && g < T_LEN) {      // g even, T_LEN even -> g+1 also valid
            float s0, s1;
            upk(sreg[p], s0, s1);
            float r0 = fmaf(fmaxf(s0, 0.0f), c1wv, c1bv);
            r0 = fmaf(fmaxf(r0, 0.0f), c2wv, c2bv);
            v0 = copysignf((__expf(fabsf(r0) * LN256) - 1.0f) * (1.0f / 255.0f), r0);
            float r1 = fmaf(fmaxf(s1, 0.0f), c1wv, c1bv);
            r1 = fmaf(fmaxf(r1, 0.0f), c2wv, c2bv);
            v1 = copysignf((__expf(fabsf(r1) * LN256) - 1.0f) * (1.0f / 255.0f), r1);
        }
        sreg[p] = pk(v0, v1);
        lmax = fmaxf(lmax, fmaxf(v0, v1));
    }

    // ---- tile max + exp-sum (reuse smem as fp32 scratch) ----
    __syncthreads();
    float* red = (float*)smem;
    red[tid] = lmax;
    __syncthreads();
    if (tid < 128) red[tid] = fmaxf(fmaxf(red[tid], red[tid + 128]), red[tid + 256]);
    __syncthreads();
    #pragma unroll
    for (int off = 64; off > 0; off >>= 1) {
        if (tid < off) red[tid] = fmaxf(red[tid], red[tid + off]);
        __syncthreads();
    }
    const float tmax = red[0];
    __syncthreads();

    float lsum = 0.0f;
    #pragma unroll
    for (int p = 0; p < NPAIR; p++) {
        float v0, v1;
        upk(sreg[p], v0, v1);
        lsum += __expf(v0 - tmax) + __expf(v1 - tmax);
    }
    red[tid] = lsum;
    __syncthreads();
    if (tid < 128) red[tid] = red[tid] + red[tid + 128] + red[tid + 256];
    __syncthreads();
    #pragma unroll
    for (int off = 64; off > 0; off >>= 1) {
        if (tid < off) red[tid] = red[tid] + red[tid + off];
        __syncthreads();
    }
    if (tid == 0) {
        g_tilemax[b * NTILES + tile] = tmax;
        g_tilesum[b * NTILES + tile] = red[0];
        __threadfence();
    }
    __syncthreads();

    // ---- software grid barrier (all 296 CTAs guaranteed co-resident) ----
    if (tid == 0) {
        volatile u32* ep = &g_epoch;
        u32 my = *ep;
        u32 t = atomicAdd(&g_arrive, 1u);
        if (t == NCTAS - 1) {
            g_arrive = 0;
            __threadfence();
            atomicAdd(&g_epoch, 1u);
        } else {
            long long guard = 0;
            while (*ep == my && guard < (1LL << 30)) { __nanosleep(64); guard++; }
        }
        __threadfence();
    }
    __syncthreads();

    // ---- per-CTA: combine all tiles of this batch -> bmax, inv ----
    {
        volatile float* vtm = (volatile float*)g_tilemax;
        volatile float* vts = (volatile float*)g_tilesum;
        float m = NEGBIG, s = 0.0f;
        if (tid < NTILES) { m = vtm[b * NTILES + tid]; s = vts[b * NTILES + tid]; }
        if (tid < 64) red[tid] = (tid < NTILES) ? m : NEGBIG;
        __syncthreads();
        #pragma unroll
        for (int off = 32; off > 0; off >>= 1) {
            if (tid < off) red[tid] = fmaxf(red[tid], red[tid + off]);
            __syncthreads();
        }
        float bmax = red[0];
        __syncthreads();
        if (tid < 64) red[tid] = (tid < NTILES) ? s * __expf(m - bmax) : 0.0f;
        __syncthreads();
        #pragma unroll
        for (int off = 32; off > 0; off >>= 1) {
            if (tid < off) red[tid] = red[tid] + red[tid + off];
            __syncthreads();
        }
        float inv = 1.0f / red[0];

        // ---- final normalized write, straight from registers ----
        #pragma unroll
        for (int p = 0; p < NPAIR; p++) {
            int q = tid + p * NTH;
            int i = 2*q;
            int g = g0 + i;
            if (i >= HALO && g < T_LEN) {
                float v0, v1;
                upk(sreg[p], v0, v1);
                float e0 = __expf(v0 - bmax) * inv;
                float e1 = __expf(v1 - bmax) * inv;
                *(float2*)(out + base + g) = make_float2(e0, e1);
            }
        }
    }
}

extern "C" void kernel_launch(void* const* d_in, const int* in_sizes, int n_in,
                              void* d_out, int out_size)
{
    const float* x   = (const float*)d_in[0];
    const float* cw  = (const float*)d_in[1];
    const float* cb  = (const float*)d_in[2];
    const float* fw  = (const float*)d_in[3];
    const float* fb  = (const float*)d_in[4];
    const float* gw  = (const float*)d_in[5];
    const float* gb  = (const float*)d_in[6];
    const float* rw  = (const float*)d_in[7];
    const float* rb  = (const float*)d_in[8];
    const float* c1w = (const float*)d_in[9];
    const float* c1b = (const float*)d_in[10];
    const float* c2w = (const float*)d_in[11];
    const float* c2b = (const float*)d_in[12];
    float* out = (float*)d_out;

    cudaFuncSetAttribute(wavenet_k1, cudaFuncAttributeMaxDynamicSharedMemorySize, SMEM_BYTES);

    wavenet_k1<<<dim3(NTILES, BATCH), NTH, SMEM_BYTES>>>(
        x, cw, cb, fw, fb, gw, gb, rw, rb, c1w, c1b, c2w, c2b, out);
}

// round 5
// speedup vs baseline: 2.0081x; 1.0821x over previous
#include <cuda_runtime.h>
#include <cuda_fp16.h>

#define N_LAYERS 30
#define T_LEN    262144
#define BATCH    8
#define NTH      384
#define NPAIR    10
#define LEXT     7680                    // NTH*2*NPAIR
#define HALO     576
#define TILE     (LEXT - HALO)           // 7104
#define NTILES   37
#define NCTAS    (NTILES * BATCH)        // 296 = 148 SMs x occ 2
#define PADL     32                      // zero-pad samples (max lookback 32)
#define PADW     (PADL/2)                // 16 words
#define BUFU32   (PADW + LEXT/2)         // 3856 words per f16x2 buffer
#define WOFFB    (2 * BUFU32 * 4)
#define SMEM_BYTES (WOFFB + 448 * 4)     // ~32.6 KB

#define LN256  5.545177444479562f
#define NEGBIG -3.402823466e38f

typedef unsigned long long u64;
typedef unsigned int u32;

__device__ float g_tilemax[NCTAS];
__device__ float g_tilesum[NCTAS];
__device__ u32   g_arrive;   // zero-init
__device__ u32   g_epoch;    // zero-init

// ---------- f32x2 helpers (epilogue only) ----------
__device__ __forceinline__ u64 pk(float lo, float hi) {
    u64 r; asm("mov.b64 %0,{%1,%2};" : "=l"(r) : "f"(lo), "f"(hi)); return r;
}
__device__ __forceinline__ void upk(u64 v, float& lo, float& hi) {
    asm("mov.b64 {%0,%1},%2;" : "=f"(lo), "=f"(hi) : "l"(v));
}

// ---------- f16x2 helpers ----------
__device__ __forceinline__ u32 hfma2(u32 a, u32 b, u32 c) {
    u32 d; asm("fma.rn.f16x2 %0,%1,%2,%3;" : "=r"(d) : "r"(a), "r"(b), "r"(c)); return d;
}
__device__ __forceinline__ u32 hmul2(u32 a, u32 b) {
    u32 d; asm("mul.rn.f16x2 %0,%1,%2;" : "=r"(d) : "r"(a), "r"(b)); return d;
}
__device__ __forceinline__ u32 hadd2(u32 a, u32 b) {
    u32 d; asm("add.rn.f16x2 %0,%1,%2;" : "=r"(d) : "r"(a), "r"(b)); return d;
}
__device__ __forceinline__ u32 htanh2(u32 a) {
    u32 d; asm("tanh.approx.f16x2 %0,%1;" : "=r"(d) : "r"(a)); return d;
}
// pack two f32 -> f16x2 (lo = first arg)
__device__ __forceinline__ u32 pkh(float lo, float hi) {
    u32 d; asm("cvt.rn.f16x2.f32 %0,%1,%2;" : "=r"(d) : "f"(hi), "f"(lo)); return d;
}
__device__ __forceinline__ u32 duph(float w) {
    u32 d; asm("cvt.rn.f16x2.f32 %0,%1,%1;" : "=r"(d) : "f"(w)); return d;
}
__device__ __forceinline__ float2 uph(u32 v) {
    __half2 h = *reinterpret_cast<__half2*>(&v);
    return __half22float2(h);
}
// misaligned f16x2: (a.hi, b.lo)
__device__ __forceinline__ u32 prmt5432(u32 a, u32 b) {
    u32 d; asm("prmt.b32 %0,%1,%2,0x5432;" : "=r"(d) : "r"(a), "r"(b)); return d;
}

// One gated residual layer, even dilation D (samples), f16x2 everywhere.
template<int D, bool STORE>
__device__ __forceinline__ void layer_even(int k, const u32* cur, u32* nxt,
                                           const float* ws, int tid, bool zh,
                                           u32* hreg, u32* sreg, u32 halfh)
{
    const u32 fw0 = duph(ws[8+5*k]),  fw1 = duph(ws[9+5*k]),  fw2 = duph(ws[10+5*k]);
    const u32 fw3 = duph(ws[11+5*k]), fw4 = duph(ws[12+5*k]);
    const u32 gw0 = duph(ws[188+5*k]), gw1 = duph(ws[189+5*k]), gw2 = duph(ws[190+5*k]);
    const u32 gw3 = duph(ws[191+5*k]), gw4 = duph(ws[192+5*k]);
    const u32 fb2 = duph(ws[158+k]), gb2 = duph(ws[338+k]);
    u32 rw2 = 0, rb2 = 0;
    if (STORE) { rw2 = duph(ws[368+k]); rb2 = duph(ws[398+k]); }

    #pragma unroll
    for (int p = 0; p < NPAIR; p++) {
        int q = tid + p * NTH;
        const u32* s = cur + PADW + q;
        u32 t1 = s[-(D/2)];
        u32 t2 = s[-D];
        u32 t3 = s[-(3*D/2)];
        u32 t4 = s[-2*D];
        u32 t0 = hreg[p];

        u32 fp = hfma2(fw4, t0, hfma2(fw3, t1, hfma2(fw2, t2, hfma2(fw1, t3, hfma2(fw0, t4, fb2)))));
        u32 gp = hfma2(gw4, t0, hfma2(gw3, t1, hfma2(gw2, t2, hfma2(gw1, t3, hfma2(gw0, t4, gb2)))));

        u32 f2v = htanh2(fp);
        u32 g2v = hfma2(htanh2(gp), halfh, halfh);   // sigmoid (gate pre-scaled 0.5)
        u32 z   = hmul2(f2v, g2v);
        sreg[p] = hadd2(sreg[p], z);
        if (STORE) {
            u32 hn = hfma2(z, rw2, hadd2(t0, rb2));
            if (zh && 2*q < HALO) hn = 0u;
            hreg[p] = hn;
            nxt[PADW + q] = hn;
        }
    }
    if (STORE) __syncthreads();
}

__global__ __launch_bounds__(NTH, 2)
void wavenet_k1(const float* __restrict__ x,
                const float* __restrict__ cw,  const float* __restrict__ cb,
                const float* __restrict__ fw,  const float* __restrict__ fb,
                const float* __restrict__ gw,  const float* __restrict__ gb,
                const float* __restrict__ rw,  const float* __restrict__ rb,
                const float* __restrict__ c1w, const float* __restrict__ c1b,
                const float* __restrict__ c2w, const float* __restrict__ c2b,
                float* __restrict__ out)
{
    extern __shared__ char smem[];
    u32*   b0 = (u32*)smem;
    u32*   b1 = b0 + BUFU32;
    float* ws = (float*)(smem + WOFFB);

    const int tid  = threadIdx.x;
    const int tile = blockIdx.x;
    const int b    = blockIdx.y;
    const long long base = (long long)b * T_LEN;
    const int g0 = tile * TILE - HALO;
    const bool zh = (tile == 0);

    // ---- weights -> smem (gate pre-scaled by 0.5, exact) ----
    if (tid < 5)  ws[tid] = cw[tid];
    if (tid == 5) ws[5]   = cb[0];
    for (int j = tid; j < 150; j += NTH) { ws[8 + j] = fw[j]; ws[188 + j] = gw[j] * 0.5f; }
    for (int j = tid; j < 30;  j += NTH) {
        ws[158 + j] = fb[j]; ws[338 + j] = gb[j] * 0.5f;
        ws[368 + j] = rw[j]; ws[398 + j] = rb[j];
    }
    if (tid == 0) { ws[428] = c1w[0]; ws[429] = c1b[0]; ws[430] = c2w[0]; ws[431] = c2b[0]; }

    if (tid < PADW) { b0[tid] = 0u; b1[tid] = 0u; }

    // ---- stage x -> f16x2 buf0 ----
    #pragma unroll
    for (int p = 0; p < NPAIR; p++) {
        int q = tid + p * NTH;
        int g = g0 + 2*q;
        float2 v;
        if (g >= 0 && g + 1 < T_LEN) {
            v = *(const float2*)(x + base + g);
        } else {
            v.x = (g     >= 0 && g     < T_LEN) ? x[base + g]     : 0.0f;
            v.y = (g + 1 >= 0 && g + 1 < T_LEN) ? x[base + g + 1] : 0.0f;
        }
        b0[PADW + q] = pkh(v.x, v.y);
    }
    __syncthreads();

    const u32 halfh = duph(0.5f);
    u32 hreg[NPAIR];
    u32 sreg[NPAIR];

    // ---- causal conv (d=1): b0 -> b1 + hreg ----
    {
        const u32 w02 = duph(ws[0]), w12 = duph(ws[1]), w22 = duph(ws[2]),
                  w32 = duph(ws[3]), w42 = duph(ws[4]), bc2 = duph(ws[5]);
        #pragma unroll
        for (int p = 0; p < NPAIR; p++) {
            int q = tid + p * NTH;
            const u32* s = b0 + PADW + q;
            u32 t0  = s[0];
            u32 wm1 = s[-1];
            u32 wm2 = s[-2];
            u32 t1 = prmt5432(wm1, t0);    // samples (2q-1, 2q)
            u32 t2 = wm1;                  // (2q-2, 2q-1)
            u32 t3 = prmt5432(wm2, wm1);   // (2q-3, 2q-2)
            u32 t4 = wm2;                  // (2q-4, 2q-3)
            u32 v = hfma2(w42, t0, hfma2(w32, t1, hfma2(w22, t2, hfma2(w12, t3, hfma2(w02, t4, bc2)))));
            if (zh && 2*q < HALO) v = 0u;
            hreg[p] = v;
            sreg[p] = 0u;
            b1[PADW + q] = v;
        }
    }
    __syncthreads();

    u32* cur = b1;
    u32* nxt = b0;

    // ---- layer 0 (d=1): odd offsets via PRMT ----
    {
        const u32 fw0 = duph(ws[8]),   fw1 = duph(ws[9]),   fw2 = duph(ws[10]);
        const u32 fw3 = duph(ws[11]),  fw4 = duph(ws[12]);
        const u32 gw0 = duph(ws[188]), gw1 = duph(ws[189]), gw2 = duph(ws[190]);
        const u32 gw3 = duph(ws[191]), gw4 = duph(ws[192]);
        const u32 fb2 = duph(ws[158]), gb2 = duph(ws[338]);
        const u32 rw2 = duph(ws[368]), rb2 = duph(ws[398]);
        #pragma unroll
        for (int p = 0; p < NPAIR; p++) {
            int q = tid + p * NTH;
            const u32* s = cur + PADW + q;
            u32 t0  = hreg[p];
            u32 wm1 = s[-1];
            u32 wm2 = s[-2];
            u32 t1 = prmt5432(wm1, t0);
            u32 t2 = wm1;
            u32 t3 = prmt5432(wm2, wm1);
            u32 t4 = wm2;

            u32 fp = hfma2(fw4, t0, hfma2(fw3, t1, hfma2(fw2, t2, hfma2(fw1, t3, hfma2(fw0, t4, fb2)))));
            u32 gp = hfma2(gw4, t0, hfma2(gw3, t1, hfma2(gw2, t2, hfma2(gw1, t3, hfma2(gw0, t4, gb2)))));

            u32 f2v = htanh2(fp);
            u32 g2v = hfma2(htanh2(gp), halfh, halfh);
            u32 z   = hmul2(f2v, g2v);
            sreg[p] = hadd2(sreg[p], z);
            u32 hn  = hfma2(z, rw2, hadd2(t0, rb2));
            if (zh && 2*q < HALO) hn = 0u;
            hreg[p] = hn;
            nxt[PADW + q] = hn;
        }
        __syncthreads();
        u32* tmp = cur; cur = nxt; nxt = tmp;
    }

    // ---- layers 1..28: static dilation cycle (2,4,8,6) x 7 ----
    int k = 1;
    #pragma unroll 1
    for (int j = 0; j < 7; j++) {
        layer_even<2, true>(k,   cur, nxt, ws, tid, zh, hreg, sreg, halfh);
        { u32* t = cur; cur = nxt; nxt = t; }
        layer_even<4, true>(k+1, cur, nxt, ws, tid, zh, hreg, sreg, halfh);
        { u32* t = cur; cur = nxt; nxt = t; }
        layer_even<8, true>(k+2, cur, nxt, ws, tid, zh, hreg, sreg, halfh);
        { u32* t = cur; cur = nxt; nxt = t; }
        layer_even<6, true>(k+3, cur, nxt, ws, tid, zh, hreg, sreg, halfh);
        { u32* t = cur; cur = nxt; nxt = t; }
        k += 4;
    }
    // ---- layer 29 (d=2): skips only ----
    layer_even<2, false>(29, cur, nxt, ws, tid, zh, hreg, sreg, halfh);

    // ---- epilogue: 1x1 convs + mu-law (f32); v kept packed in vreg ----
    const float c1wv = ws[428], c1bv = ws[429], c2wv = ws[430], c2bv = ws[431];
    u64 vreg[NPAIR];
    float lmax = NEGBIG;
    #pragma unroll
    for (int p = 0; p < NPAIR; p++) {
        int q = tid + p * NTH;
        int i = 2*q;
        int g = g0 + i;
        float v0 = NEGBIG, v1 = NEGBIG;
        if (i >= HALO && g < T_LEN) {
            float2 sv = uph(sreg[p]);
            float r0 = fmaf(fmaxf(sv.x, 0.0f), c1wv, c1bv);
            r0 = fmaf(fmaxf(r0, 0.0f), c2wv, c2bv);
            v0 = copysignf((__expf(fabsf(r0) * LN256) - 1.0f) * (1.0f / 255.0f), r0);
            float r1 = fmaf(fmaxf(sv.y, 0.0f), c1wv, c1bv);
            r1 = fmaf(fmaxf(r1, 0.0f), c2wv, c2bv);
            v1 = copysignf((__expf(fabsf(r1) * LN256) - 1.0f) * (1.0f / 255.0f), r1);
        }
        vreg[p] = pk(v0, v1);
        lmax = fmaxf(lmax, fmaxf(v0, v1));
    }

    // ---- tile max + exp-sum (reuse smem as fp32 scratch) ----
    __syncthreads();
    float* red = (float*)smem;
    red[tid] = lmax;
    __syncthreads();
    if (tid < 128) red[tid] = fmaxf(fmaxf(red[tid], red[tid + 128]), red[tid + 256]);
    __syncthreads();
    #pragma unroll
    for (int off = 64; off > 0; off >>= 1) {
        if (tid < off) red[tid] = fmaxf(red[tid], red[tid + off]);
        __syncthreads();
    }
    const float tmax = red[0];
    __syncthreads();

    float lsum = 0.0f;
    #pragma unroll
    for (int p = 0; p < NPAIR; p++) {
        float v0, v1;
        upk(vreg[p], v0, v1);
        lsum += __expf(v0 - tmax) + __expf(v1 - tmax);
    }
    red[tid] = lsum;
    __syncthreads();
    if (tid < 128) red[tid] = red[tid] + red[tid + 128] + red[tid + 256];
    __syncthreads();
    #pragma unroll
    for (int off = 64; off > 0; off >>= 1) {
        if (tid < off) red[tid] = red[tid] + red[tid + off];
        __syncthreads();
    }
    if (tid == 0) {
        g_tilemax[b * NTILES + tile] = tmax;
        g_tilesum[b * NTILES + tile] = red[0];
        __threadfence();
    }
    __syncthreads();

    // ---- software grid barrier (all 296 CTAs co-resident) ----
    if (tid == 0) {
        volatile u32* ep = &g_epoch;
        u32 my = *ep;
        u32 t = atomicAdd(&g_arrive, 1u);
        if (t == NCTAS - 1) {
            g_arrive = 0;
            __threadfence();
            atomicAdd(&g_epoch, 1u);
        } else {
            long long guard = 0;
            while (*ep == my && guard < (1LL << 30)) { __nanosleep(64); guard++; }
        }
        __threadfence();
    }
    __syncthreads();

    // ---- combine all tiles of this batch -> bmax, inv; final write ----
    {
        volatile float* vtm = (volatile float*)g_tilemax;
        volatile float* vts = (volatile float*)g_tilesum;
        float m = NEGBIG, s = 0.0f;
        if (tid < NTILES) { m = vtm[b * NTILES + tid]; s = vts[b * NTILES + tid]; }
        if (tid < 64) red[tid] = (tid < NTILES) ? m : NEGBIG;
        __syncthreads();
        #pragma unroll
        for (int off = 32; off > 0; off >>= 1) {
            if (tid < off) red[tid] = fmaxf(red[tid], red[tid + off]);
            __syncthreads();
        }
        float bmax = red[0];
        __syncthreads();
        if (tid < 64) red[tid] = (tid < NTILES) ? s * __expf(m - bmax) : 0.0f;
        __syncthreads();
        #pragma unroll
        for (int off = 32; off > 0; off >>= 1) {
            if (tid < off) red[tid] = red[tid] + red[tid + off];
            __syncthreads();
        }
        float inv = 1.0f / red[0];

        #pragma unroll
        for (int p = 0; p < NPAIR; p++) {
            int q = tid + p * NTH;
            int i = 2*q;
            int g = g0 + i;
            if (i >= HALO && g < T_LEN) {
                float v0, v1;
                upk(vreg[p], v0, v1);
                float e0 = __expf(v0 - bmax) * inv;
                float e1 = __expf(v1 - bmax) * inv;
                *(float2*)(out + base + g) = make_float2(e0, e1);
            }
        }
    }
}

extern "C" void kernel_launch(void* const* d_in, const int* in_sizes, int n_in,
                              void* d_out, int out_size)
{
    const float* x   = (const float*)d_in[0];
    const float* cw  = (const float*)d_in[1];
    const float* cb  = (const float*)d_in[2];
    const float* fw  = (const float*)d_in[3];
    const float* fb  = (const float*)d_in[4];
    const float* gw  = (const float*)d_in[5];
    const float* gb  = (const float*)d_in[6];
    const float* rw  = (const float*)d_in[7];
    const float* rb  = (const float*)d_in[8];
    const float* c1w = (const float*)d_in[9];
    const float* c1b = (const float*)d_in[10];
    const float* c2w = (const float*)d_in[11];
    const float* c2b = (const float*)d_in[12];
    float* out = (float*)d_out;

    cudaFuncSetAttribute(wavenet_k1, cudaFuncAttributeMaxDynamicSharedMemorySize, SMEM_BYTES);

    wavenet_k1<<<dim3(NTILES, BATCH), NTH, SMEM_BYTES>>>(
        x, cw, cb, fw, fb, gw, gb, rw, rb, c1w, c1b, c2w, c2b, out);
}